// round 1
// baseline (speedup 1.0000x reference)
#include <cuda_runtime.h>

#define B_   64
#define S_   2048
#define H_   1024
#define SPLIT 16
#define CHUNK (S_ / SPLIT)      // 128 timesteps per CTA
#define WARPS 8
#define THREADS 256

// Scratch (allocation-free: __device__ globals)
__device__ float g_expE [B_ * S_];            // exp(tanh(score)) per (b,s)
__device__ float g_partL[B_ * SPLIT];          // partial sum of exp per chunk
__device__ float g_partC[B_ * SPLIT * H_];     // partial context per chunk (4 MiB)
__device__ float g_linv [B_];                  // 1 / sum_exp per batch

// ---------------------------------------------------------------------------
// Pass 1: single read of rnn_output. Each warp handles one timestep at a time:
//   dot(x_s, w) via float4 loads + warp shuffle reduce, then t = exp(tanh(.)),
//   accumulate lsum += t and cacc[h] += t * x_s[h] (x reused from registers).
// tanh output is in [-1,1] so softmax needs no max subtraction.
// ---------------------------------------------------------------------------
__global__ __launch_bounds__(THREADS)
void pass1_kernel(const float* __restrict__ x,
                  const float* __restrict__ w,
                  const float* __restrict__ bptr)
{
    __shared__ float ws[H_];                 // 4 KB weight cache
    __shared__ float red[WARPS * H_];        // 32 KB cross-warp reduction
    __shared__ float lred[WARPS];

    const int b     = blockIdx.x / SPLIT;
    const int chunk = blockIdx.x % SPLIT;
    const int tid   = threadIdx.x;
    const int warp  = tid >> 5;
    const int lane  = tid & 31;
    const float bias = __ldg(bptr);

    // stage w into smem
    for (int i = tid; i < H_ / 4; i += THREADS)
        reinterpret_cast<float4*>(ws)[i] =
            reinterpret_cast<const float4*>(w)[i];
    __syncthreads();

    float cacc[8][4];
    #pragma unroll
    for (int i = 0; i < 8; i++) {
        cacc[i][0] = 0.f; cacc[i][1] = 0.f; cacc[i][2] = 0.f; cacc[i][3] = 0.f;
    }
    float lsum = 0.f;

    const int s0 = chunk * CHUNK;

    #pragma unroll 1
    for (int it = 0; it < CHUNK / WARPS; it++) {
        const int s = s0 + it * WARPS + warp;
        const float4* xp = reinterpret_cast<const float4*>(
            x + ((size_t)b * S_ + s) * H_);

        float4 xr[8];
        float dot = 0.f;
        #pragma unroll
        for (int i = 0; i < 8; i++) {
            xr[i] = xp[i * 32 + lane];                       // coalesced 512B/iter
            float4 wv = reinterpret_cast<float4*>(ws)[i * 32 + lane];
            dot += xr[i].x * wv.x + xr[i].y * wv.y
                 + xr[i].z * wv.z + xr[i].w * wv.w;
        }
        // warp reduce
        #pragma unroll
        for (int off = 16; off; off >>= 1)
            dot += __shfl_xor_sync(0xffffffffu, dot, off);

        const float t = __expf(tanhf(dot + bias));
        if (lane == 0) g_expE[(size_t)b * S_ + s] = t;
        lsum += t;

        #pragma unroll
        for (int i = 0; i < 8; i++) {
            cacc[i][0] += t * xr[i].x;
            cacc[i][1] += t * xr[i].y;
            cacc[i][2] += t * xr[i].z;
            cacc[i][3] += t * xr[i].w;
        }
    }

    // per-warp partials -> smem
    #pragma unroll
    for (int i = 0; i < 8; i++) {
        float4 v = make_float4(cacc[i][0], cacc[i][1], cacc[i][2], cacc[i][3]);
        reinterpret_cast<float4*>(red + warp * H_)[i * 32 + lane] = v;
    }
    if (lane == 0) lred[warp] = lsum;
    __syncthreads();

    // combine 8 warps; each thread owns one float4 of H
    for (int h4 = tid; h4 < H_ / 4; h4 += THREADS) {
        float4 acc = reinterpret_cast<float4*>(red)[h4];
        #pragma unroll
        for (int wI = 1; wI < WARPS; wI++) {
            float4 v = reinterpret_cast<float4*>(red + wI * H_)[h4];
            acc.x += v.x; acc.y += v.y; acc.z += v.z; acc.w += v.w;
        }
        reinterpret_cast<float4*>(
            g_partC + ((size_t)b * SPLIT + chunk) * H_)[h4] = acc;
    }
    if (tid == 0) {
        float l = 0.f;
        #pragma unroll
        for (int i = 0; i < WARPS; i++) l += lred[i];
        g_partL[b * SPLIT + chunk] = l;
    }
}

// ---------------------------------------------------------------------------
// Pass 2: per-batch combine of SPLIT partials -> context [B,H] and 1/l.
// ---------------------------------------------------------------------------
__global__ __launch_bounds__(THREADS)
void pass2_kernel(float* __restrict__ ctx_out)
{
    const int b   = blockIdx.x;
    const int tid = threadIdx.x;
    __shared__ float s_inv;

    if (tid < 32) {
        float l = (tid < SPLIT) ? g_partL[b * SPLIT + tid] : 0.f;
        #pragma unroll
        for (int off = 16; off; off >>= 1)
            l += __shfl_xor_sync(0xffffffffu, l, off);
        if (tid == 0) {
            float inv = 1.f / l;
            s_inv = inv;
            g_linv[b] = inv;
        }
    }
    __syncthreads();
    const float inv = s_inv;

    for (int h4 = tid; h4 < H_ / 4; h4 += THREADS) {
        float4 acc = make_float4(0.f, 0.f, 0.f, 0.f);
        #pragma unroll
        for (int c = 0; c < SPLIT; c++) {
            float4 v = reinterpret_cast<const float4*>(
                g_partC + ((size_t)b * SPLIT + c) * H_)[h4];
            acc.x += v.x; acc.y += v.y; acc.z += v.z; acc.w += v.w;
        }
        acc.x *= inv; acc.y *= inv; acc.z *= inv; acc.w *= inv;
        reinterpret_cast<float4*>(ctx_out + (size_t)b * H_)[h4] = acc;
    }
}

// ---------------------------------------------------------------------------
// Pass 3: weights[b,s] = expE[b,s] / l[b]
// ---------------------------------------------------------------------------
__global__ __launch_bounds__(THREADS)
void pass3_kernel(float* __restrict__ w_out)
{
    const int i = blockIdx.x * THREADS + threadIdx.x;  // over B*S
    if (i < B_ * S_) {
        const int b = i / S_;
        w_out[i] = g_expE[i] * g_linv[b];
    }
}

extern "C" void kernel_launch(void* const* d_in, const int* in_sizes, int n_in,
                              void* d_out, int out_size)
{
    const float* x    = (const float*)d_in[0];   // rnn_output [B,S,H]
    const float* w    = (const float*)d_in[1];   // attn_w [H]
    const float* bptr = (const float*)d_in[2];   // attn_b scalar

    float* out = (float*)d_out;                  // context [B,H] then weights [B,S]
    float* ctx_out = out;
    float* wts_out = out + (size_t)B_ * H_;

    pass1_kernel<<<B_ * SPLIT, THREADS>>>(x, w, bptr);
    pass2_kernel<<<B_, THREADS>>>(ctx_out);
    pass3_kernel<<<(B_ * S_ + THREADS - 1) / THREADS, THREADS>>>(wts_out);
}